// round 14
// baseline (speedup 1.0000x reference)
#include <cuda_runtime.h>

// Problem constants
#define BTOT   2048
#define TLEN   512
#define HDIM   64
#define G4     256          // 4*H gates
#define BBLK   16           // batches per block (128 blocks * 16 = 2048 EXACT)
#define GB     4            // batches per group (4 groups per block)
#define XC     256          // x chunk length cached in smem
#define NBLK   128          // one perfect wave, no tail masking anywhere
#define NTH    512          // 4 groups x 128 threads; each thread owns 2 gate rows
#define GS     5            // gsm batch stride (coprime with 32 => conflict-free)

// packed f32x2 FMA (sm_10x): acc.lo += w.lo*h.lo ; acc.hi += w.hi*h.hi
__device__ __forceinline__ void fma2(unsigned long long &acc,
                                     unsigned long long w,
                                     unsigned long long h) {
    asm("fma.rn.f32x2 %0, %1, %2, %0;" : "+l"(acc) : "l"(w), "l"(h));
}
__device__ __forceinline__ float2 unpack2(unsigned long long v) {
    float2 r;
    asm("mov.b64 {%0, %1}, %2;" : "=f"(r.x), "=f"(r.y) : "l"(v));
    return r;
}
__device__ __forceinline__ float sigf(float x) {
    return __fdividef(1.0f, 1.0f + __expf(-x));
}
__device__ __forceinline__ float tanhfast(float x) {
    float e = __expf(2.0f * x);
    return 1.0f - __fdividef(2.0f, e + 1.0f);
}
// named barrier over one group's 128 threads (warp-aligned groups)
__device__ __forceinline__ void gbar(int id) {
    asm volatile("bar.sync %0, %1;" :: "r"(id), "r"(128) : "memory");
}

__global__ void __launch_bounds__(NTH, 1)
lstm_fused_kernel(const float* __restrict__ x,      // [B, T, 1]
                  const float* __restrict__ W_ih,   // [4H, 1]
                  const float* __restrict__ W_hh,   // [4H, H]
                  const float* __restrict__ b_ih,   // [4H]
                  const float* __restrict__ b_hh,   // [4H]
                  const float* __restrict__ fc1_w,  // [16, H]
                  const float* __restrict__ fc1_b,  // [16]
                  const float* __restrict__ fc2_w,  // [1, 16]
                  const float* __restrict__ fc2_b,  // [1]
                  float* __restrict__ out)          // [B, 1]
{
    __shared__ __align__(16) float hsm[4][GB * HDIM];  // h_{t-1} per group (4KB)
    __shared__ float gsm[4][G4 * GS];                  // gate pre-acts    (20KB)
    __shared__ float xs[4][GB * XC];                   // x slabs          (16KB)
    __shared__ float zsm[4][GB * 16];                  // fc1 activations  (1KB)

    const int tid  = threadIdx.x;
    const int grp  = tid >> 7;             // 0..3
    const int gtid = tid & 127;            // thread-in-group
    const int bar  = grp + 1;              // named barrier id 1..4
    const int b0   = blockIdx.x * BBLK + grp * GB;  // first global batch (exact fit)
    const int gA   = gtid;                 // first owned gate row
    const int gB   = gtid + 128;           // second owned gate row

    // Two gate rows of W_hh packed into f32x2 pairs (64 registers).
    unsigned long long wA[HDIM / 2], wB[HDIM / 2];
    {
        const ulonglong2* wpA = reinterpret_cast<const ulonglong2*>(W_hh + gA * HDIM);
        const ulonglong2* wpB = reinterpret_cast<const ulonglong2*>(W_hh + gB * HDIM);
        #pragma unroll
        for (int i = 0; i < HDIM / 4; i++) {
            ulonglong2 vA = wpA[i];
            wA[2 * i] = vA.x;  wA[2 * i + 1] = vA.y;
            ulonglong2 vB = wpB[i];
            wB[2 * i] = vB.x;  wB[2 * i + 1] = vB.y;
        }
    }
    const float wihA  = W_ih[gA],            wihB  = W_ih[gB];
    const float biasA = b_ih[gA] + b_hh[gA], biasB = b_ih[gB] + b_hh[gB];

    float* hp  = hsm[grp];
    float* gsg = gsm[grp];
    float* xsg = xs[grp];

    for (int i = gtid; i < GB * HDIM; i += 128) hp[i] = 0.0f;
    float c0 = 0.0f, c1 = 0.0f;            // cell state: units gtid, gtid+128

    // prologue: load x chunk 0 (coalesced along t; no batch masking needed)
    for (int m = gtid; m < GB * XC; m += 128) {
        int b  = m >> 8;                   // / XC
        int tt = m & (XC - 1);
        xsg[m] = x[(b0 + b) * TLEN + tt];
    }
    gbar(bar);

    for (int t = 0; t < TLEN; t++) {
        const int tt = t & (XC - 1);

        // ---- gate phase: 2 rows x 4 batches; 2 batches in flight (4 chains) ----
        #pragma unroll
        for (int bp = 0; bp < 2; bp++) {
            const int b = 2 * bp;
            unsigned long long a0 = 0ULL, a1 = 0ULL, a2 = 0ULL, a3 = 0ULL;
            const ulonglong2* h0 = reinterpret_cast<const ulonglong2*>(hp + b * HDIM);
            const ulonglong2* h1 = reinterpret_cast<const ulonglong2*>(hp + (b + 1) * HDIM);
            #pragma unroll
            for (int kk = 0; kk < HDIM / 4; kk++) {
                ulonglong2 p0 = h0[kk];    // LDS.128 broadcast
                ulonglong2 p1 = h1[kk];
                fma2(a0, wA[2 * kk],     p0.x);
                fma2(a1, wB[2 * kk],     p0.x);
                fma2(a2, wA[2 * kk],     p1.x);
                fma2(a3, wB[2 * kk],     p1.x);
                fma2(a0, wA[2 * kk + 1], p0.y);
                fma2(a1, wB[2 * kk + 1], p0.y);
                fma2(a2, wA[2 * kk + 1], p1.y);
                fma2(a3, wB[2 * kk + 1], p1.y);
            }
            float2 f0 = unpack2(a0), f1 = unpack2(a1);
            float2 f2 = unpack2(a2), f3 = unpack2(a3);
            float xv0 = xsg[b * XC + tt];
            float xv1 = xsg[(b + 1) * XC + tt];
            gsg[gA * GS + b]     = f0.x + f0.y + xv0 * wihA + biasA;
            gsg[gB * GS + b]     = f1.x + f1.y + xv0 * wihB + biasB;
            gsg[gA * GS + b + 1] = f2.x + f2.y + xv1 * wihA + biasA;
            gsg[gB * GS + b + 1] = f3.x + f3.y + xv1 * wihB + biasB;
        }
        gbar(bar);

        // ---- elementwise phase: exactly 2 units/thread (256 units/group) ----
        {
            int b = gtid >> 6, j = gtid & 63;
            float gi = sigf(gsg[j * GS + b]);
            float gf = sigf(gsg[(j + 64) * GS + b]);
            float gc = tanhfast(gsg[(j + 128) * GS + b]);
            float go = sigf(gsg[(j + 192) * GS + b]);
            c0 = gf * c0 + gi * gc;
            hp[b * HDIM + j] = go * tanhfast(c0);
        }
        {
            int u = gtid + 128;
            int b = u >> 6, j = u & 63;
            float gi = sigf(gsg[j * GS + b]);
            float gf = sigf(gsg[(j + 64) * GS + b]);
            float gc = tanhfast(gsg[(j + 128) * GS + b]);
            float go = sigf(gsg[(j + 192) * GS + b]);
            c1 = gf * c1 + gi * gc;
            hp[b * HDIM + j] = go * tanhfast(c1);
        }

        // refill x slab for next chunk (only at t == XC-1)
        if (tt == XC - 1 && t + 1 < TLEN) {
            gbar(bar);                     // xs no longer being read this chunk
            const int base = t + 1;
            for (int m = gtid; m < GB * XC; m += 128) {
                int b   = m >> 8;
                int ttt = m & (XC - 1);
                xsg[m] = x[(b0 + b) * TLEN + base + ttt];
            }
        }
        gbar(bar);
    }

    // ---- MLP head (per group): z = relu(h @ fc1^T + b); out = z @ fc2^T + b ----
    if (gtid < GB * 16) {
        int b = gtid >> 4, jj = gtid & 15;
        float acc = fc1_b[jj];
        const float* wr = fc1_w + jj * HDIM;
        #pragma unroll
        for (int k = 0; k < HDIM; k++) acc += hp[b * HDIM + k] * wr[k];
        zsm[grp][gtid] = fmaxf(acc, 0.0f);
    }
    gbar(bar);
    if (gtid < GB) {
        float acc = fc2_b[0];
        #pragma unroll
        for (int jj = 0; jj < 16; jj++) acc += zsm[grp][gtid * 16 + jj] * fc2_w[jj];
        out[b0 + gtid] = acc;
    }
}

extern "C" void kernel_launch(void* const* d_in, const int* in_sizes, int n_in,
                              void* d_out, int out_size) {
    const float* x     = (const float*)d_in[0];
    const float* W_ih  = (const float*)d_in[1];
    const float* W_hh  = (const float*)d_in[2];
    const float* b_ih  = (const float*)d_in[3];
    const float* b_hh  = (const float*)d_in[4];
    const float* fc1_w = (const float*)d_in[5];
    const float* fc1_b = (const float*)d_in[6];
    const float* fc2_w = (const float*)d_in[7];
    const float* fc2_b = (const float*)d_in[8];
    float* out = (float*)d_out;

    lstm_fused_kernel<<<NBLK, NTH>>>(x, W_ih, W_hh, b_ih, b_hh,
                                     fc1_w, fc1_b, fc2_w, fc2_b, out);
}